// round 15
// baseline (speedup 1.0000x reference)
#include <cuda_runtime.h>
#include <math.h>

// Problem constants
#define BB 64
#define NN 16
#define PP 20
#define NBB 30
#define CC 1024
#define FF 14
#define RR 1088          // BB*(NN+1) ROIs: [0,1024) individual, [1024,1088) global
#define K1 9216          // CC*9
#define NC1 4608         // 512*9
#define NC2 2304         // 256*9

// ---------------- scratch (static device globals; no allocation) ----------------
__device__ __align__(256) float g_X   [(size_t)RR * K1];          // roi-align output  [r][ci*9+p]
__device__ __align__(256) float g_W2a [(size_t)K1 * NC1];         // expanded conv1 weights
__device__ __align__(256) float g_Y1  [(size_t)RR * NC1];         // conv1+bn+leaky out
__device__ __align__(256) float g_W2b [(size_t)NC1 * NC2];        // expanded conv2 weights
__device__ __align__(256) float g_Y2  [(size_t)RR * NC2];         // conv2+bn+leaky out (i_feat / g_feat)
__device__ __align__(256) float g_Bh  [(size_t)PP * 66 * NC2];    // behavior, zero-padded along b
__device__ __align__(256) float g_W1T [(size_t)3 * NC2 * NC2];    // conv1d weights transposed [dt*2304+ki][ko]
__device__ __align__(256) float g_Xc  [(size_t)PP * 64 * NC2];    // conv1d out [p*64+b][ko]
__device__ __align__(256) float g_Ft  [(size_t)BB * NN * NC2];    // gathered feats
__device__ __align__(256) float g_H   [(size_t)BB * NN * 1024];   // fc1 out
__device__ float g_s1[512], g_t1[512], g_s2[256], g_t2[256];

// ---------------- BN scale/shift precompute ----------------
__global__ void bn_prep(const float* __restrict__ g, const float* __restrict__ b,
                        const float* __restrict__ m, const float* __restrict__ v,
                        float* __restrict__ s, float* __restrict__ t, int n) {
    int i = blockIdx.x * blockDim.x + threadIdx.x;
    if (i < n) {
        float sc = g[i] * rsqrtf(v[i] + 1e-5f);
        s[i] = sc;
        t[i] = b[i] - m[i] * sc;
    }
}

// ---------------- conv weight expansion to dense GEMM weights ----------------
// W2[(ci*9+p)*(Cout*9) + co*9+q] = w[co][ci][py-oy+1][px-ox+1] (0 if stencil OOB)
__global__ void expand_w(const float* __restrict__ w, float* __restrict__ W2,
                         int Cin, int Cout) {
    size_t total = (size_t)Cin * 9 * Cout * 9;
    int ncol = Cout * 9;
    for (size_t i = (size_t)blockIdx.x * blockDim.x + threadIdx.x; i < total;
         i += (size_t)gridDim.x * blockDim.x) {
        int col = (int)(i % ncol);
        size_t row = i / ncol;
        int p  = (int)(row % 9);
        int ci = (int)(row / 9);
        int q  = col % 9;
        int co = col / 9;
        int ky = (p / 3) - (q / 3) + 1;
        int kx = (p % 3) - (q % 3) + 1;
        float val = 0.f;
        if ((unsigned)ky < 3u && (unsigned)kx < 3u)
            val = w[(((size_t)co * Cin + ci) * 3 + ky) * 3 + kx];
        W2[i] = val;
    }
}

// conv1d weights [ko][ki][dt] -> WT[(dt*2304+ki)][ko]
__global__ void transpose_w1d(const float* __restrict__ w, float* __restrict__ WT) {
    size_t total = (size_t)3 * NC2 * NC2;
    for (size_t i = (size_t)blockIdx.x * blockDim.x + threadIdx.x; i < total;
         i += (size_t)gridDim.x * blockDim.x) {
        int ko = (int)(i % NC2);
        size_t rest = i / NC2;
        int ki = (int)(rest % NC2);
        int dt = (int)(rest / NC2);
        WT[i] = w[((size_t)ko * NC2 + ki) * 3 + dt];
    }
}

// ---------------- ROI align ----------------
// One block per ROI. r in [0,1024): individual (b = r/16, box from input);
// r in [1024,1088): global box (0,0,14,14), b = r-1024.
__global__ void roi_kernel(const float* __restrict__ fmap, const float* __restrict__ boxes,
                           float* __restrict__ X) {
    int r = blockIdx.x;
    int b;
    float bx1, by1, bx2, by2;
    if (r >= BB * NN) {
        b = r - BB * NN;
        bx1 = 0.f; by1 = 0.f; bx2 = (float)FF; by2 = (float)FF;
    } else {
        b = r / NN;
        const float* p = boxes + (size_t)r * 4;
        bx1 = p[0]; by1 = p[1]; bx2 = p[2]; by2 = p[3];
    }
    __shared__ int   i0s[12], i1s[12];
    __shared__ float wgt[12];
    int tid = threadIdx.x;
    if (tid < 12) {
        int s = tid % 6;
        bool isY = tid < 6;
        float lo  = isY ? by1 : bx1;
        float hi  = isY ? by2 : bx2;
        float ext = fmaxf(hi - lo, 1.0f);
        // pos = (s+0.5)/SR * (ext/OUT), SR=2 OUT=3
        float v = lo + (s + 0.5f) * 0.5f * (ext * (1.0f / 3.0f));
        v = fminf(fmaxf(v, 0.0f), 13.0f);
        float fl = floorf(v);
        int i0 = (int)fl;
        i0s[tid] = i0;
        i1s[tid] = min(i0 + 1, 13);
        wgt[tid] = v - fl;
    }
    __syncthreads();
    const float* fm = fmap + (size_t)b * (CC * FF * FF);
    float* xr = X + (size_t)r * K1;
    for (int idx = tid; idx < CC * 9; idx += blockDim.x) {
        int c = idx / 9, q = idx - c * 9;
        int oy = q / 3, ox = q - oy * 3;
        const float* f = fm + c * (FF * FF);
        float acc = 0.f;
#pragma unroll
        for (int dy = 0; dy < 2; dy++) {
            int sy = oy * 2 + dy;
            int ya = i0s[sy], yb = i1s[sy];
            float wy = wgt[sy];
#pragma unroll
            for (int dx = 0; dx < 2; dx++) {
                int sx = ox * 2 + dx;
                int xa = i0s[6 + sx], xb = i1s[6 + sx];
                float wx = wgt[6 + sx];
                float v00 = f[ya * FF + xa], v01 = f[ya * FF + xb];
                float v10 = f[yb * FF + xa], v11 = f[yb * FF + xb];
                float top = v00 + (v01 - v00) * wx;
                float bot = v10 + (v11 - v10) * wx;
                acc += top + (bot - top) * wy;
            }
        }
        xr[c * 9 + q] = acc * 0.25f;
    }
}

// ---------------- behavior assemble (deterministic, no atomics) ----------------
// Bh[p][bb][k], bb=0..65; bb=0/65 zero pad; bb=b+1 real batch b.
// Bh[p][b+1][k] = g_feat[b][k] + sum_{n: pid[b,n]==p} i_feat[b,n][k]
__global__ void assemble_bh(const float* __restrict__ Y2, const int* __restrict__ pid,
                            float* __restrict__ Bh) {
    int blk = blockIdx.x;          // 0..PP*66-1
    int p = blk / 66, bb = blk % 66;
    float* dst = Bh + (size_t)blk * NC2;
    if (bb == 0 || bb == 65) {
        for (int k = threadIdx.x; k < NC2; k += blockDim.x) dst[k] = 0.f;
        return;
    }
    int b = bb - 1;
    __shared__ int rows[NN];
    __shared__ int cnt;
    if (threadIdx.x == 0) {
        int c = 0;
        for (int n = 0; n < NN; n++)
            if (pid[b * NN + n] == p) rows[c++] = b * NN + n;
        cnt = c;
    }
    __syncthreads();
    const float* gsrc = Y2 + (size_t)(BB * NN + b) * NC2;
    int c = cnt;
    for (int k = threadIdx.x; k < NC2; k += blockDim.x) {
        float v = gsrc[k];
        for (int j = 0; j < c; j++) v += Y2[(size_t)rows[j] * NC2 + k];
        dst[k] = v;
    }
}

// feats[(b*16+n)][k] = Xc[(pid[b,n]*64 + b)][k]
__global__ void gather_feats(const float* __restrict__ Xc, const int* __restrict__ pid,
                             float* __restrict__ feats) {
    int m = blockIdx.x;            // 0..1023
    int b = m / NN;
    int p = pid[m];
    const float* src = Xc + ((size_t)p * 64 + b) * NC2;
    float* dst = feats + (size_t)m * NC2;
    for (int k = threadIdx.x; k < NC2; k += blockDim.x) dst[k] = src[k];
}

// ---------------- generic tiled SGEMM with fused epilogue ----------------
// C[M,N] = A[M,K] * B[K,N]
// A logical row m lives at A + (m/grp)*gstride + (m%grp)*lda (overlapping rows OK).
// Requires lda%4==0, gstride%4==0, K%16==0, A base 16B-aligned. B/C arbitrary.
// Epilogue: x = x*escale[n/ediv] + eshift[n/ediv]; act: 0=none 1=leaky(0.1) 2=relu.
__global__ __launch_bounds__(256, 2)
void sgemm(const float* __restrict__ A, const float* __restrict__ Bm,
           float* __restrict__ C,
           int M, int N, int K,
           int lda, int ldb, int ldc,
           int grp, long long gstride,
           const float* __restrict__ escale, const float* __restrict__ eshift,
           int ediv, int act) {
    const int BM = 128, BN = 128, BK = 16;
    __shared__ float As[BK][BM + 4];
    __shared__ float Bs[BK][BN];
    int t = threadIdx.x;
    int n0 = blockIdx.x * BN;
    int m0 = blockIdx.y * BM;
    int tx = t % 16, ty = t / 16;
    float acc[8][8];
#pragma unroll
    for (int i = 0; i < 8; i++)
#pragma unroll
        for (int j = 0; j < 8; j++) acc[i][j] = 0.f;

    int arow0 = t >> 2;            // 0..63
    int acol  = (t & 3) * 4;       // 0,4,8,12
    int bcol  = t % 128;
    int brow0 = t / 128;           // 0 or 1

    for (int k0 = 0; k0 < K; k0 += BK) {
        // A tile: 2 x float4 per thread
#pragma unroll
        for (int i = 0; i < 2; i++) {
            int lrow = arow0 + i * 64;
            int gm = m0 + lrow;
            float4 v = make_float4(0.f, 0.f, 0.f, 0.f);
            if (gm < M) {
                long long base = (long long)(gm / grp) * gstride +
                                 (long long)(gm % grp) * (long long)lda;
                v = *reinterpret_cast<const float4*>(A + base + k0 + acol);
            }
            As[acol + 0][lrow] = v.x;
            As[acol + 1][lrow] = v.y;
            As[acol + 2][lrow] = v.z;
            As[acol + 3][lrow] = v.w;
        }
        // B tile: 8 scalars per thread (coalesced, N-tail predicated)
        int gn = n0 + bcol;
#pragma unroll
        for (int i = 0; i < 8; i++) {
            int lrow = brow0 + i * 2;
            float v = 0.f;
            if (gn < N) v = Bm[(long long)(k0 + lrow) * ldb + gn];
            Bs[lrow][bcol] = v;
        }
        __syncthreads();
#pragma unroll
        for (int k = 0; k < BK; k++) {
            float4 a0 = *reinterpret_cast<const float4*>(&As[k][ty * 8]);
            float4 a1 = *reinterpret_cast<const float4*>(&As[k][ty * 8 + 4]);
            float4 b0 = *reinterpret_cast<const float4*>(&Bs[k][tx * 8]);
            float4 b1 = *reinterpret_cast<const float4*>(&Bs[k][tx * 8 + 4]);
            float av[8] = {a0.x, a0.y, a0.z, a0.w, a1.x, a1.y, a1.z, a1.w};
            float bv[8] = {b0.x, b0.y, b0.z, b0.w, b1.x, b1.y, b1.z, b1.w};
#pragma unroll
            for (int i = 0; i < 8; i++)
#pragma unroll
                for (int j = 0; j < 8; j++)
                    acc[i][j] = fmaf(av[i], bv[j], acc[i][j]);
        }
        __syncthreads();
    }
    // epilogue + store
#pragma unroll
    for (int i = 0; i < 8; i++) {
        int gm = m0 + ty * 8 + i;
        if (gm >= M) continue;
#pragma unroll
        for (int j = 0; j < 8; j++) {
            int gn = n0 + tx * 8 + j;
            if (gn >= N) continue;
            float x = acc[i][j];
            if (escale) x *= escale[gn / ediv];
            if (eshift) x += eshift[gn / ediv];
            if (act == 1) x = x > 0.f ? x : 0.1f * x;
            else if (act == 2) x = x > 0.f ? x : 0.f;
            C[(long long)gm * ldc + gn] = x;
        }
    }
}

// ---------------- launch ----------------
extern "C" void kernel_launch(void* const* d_in, const int* in_sizes, int n_in,
                              void* d_out, int out_size) {
    const float* fmap     = (const float*)d_in[0];
    const float* boxes    = (const float*)d_in[1];
    const int*   pid      = (const int*)  d_in[2];
    const float* conv1_w  = (const float*)d_in[3];
    const float* bn1g     = (const float*)d_in[4];
    const float* bn1b     = (const float*)d_in[5];
    const float* bn1m     = (const float*)d_in[6];
    const float* bn1v     = (const float*)d_in[7];
    const float* conv2_w  = (const float*)d_in[8];
    const float* bn2g     = (const float*)d_in[9];
    const float* bn2b     = (const float*)d_in[10];
    const float* bn2m     = (const float*)d_in[11];
    const float* bn2v     = (const float*)d_in[12];
    const float* conv1d_w = (const float*)d_in[13];
    const float* conv1d_b = (const float*)d_in[14];
    const float* fc1_w    = (const float*)d_in[15];
    const float* fc1_b    = (const float*)d_in[16];
    const float* fc2_w    = (const float*)d_in[17];
    const float* fc2_b    = (const float*)d_in[18];
    float* out = (float*)d_out;

    float *X, *W2a, *Y1, *W2b, *Y2, *Bh, *W1T, *Xc, *Ft, *H, *s1, *t1, *s2, *t2;
    cudaGetSymbolAddress((void**)&X,   g_X);
    cudaGetSymbolAddress((void**)&W2a, g_W2a);
    cudaGetSymbolAddress((void**)&Y1,  g_Y1);
    cudaGetSymbolAddress((void**)&W2b, g_W2b);
    cudaGetSymbolAddress((void**)&Y2,  g_Y2);
    cudaGetSymbolAddress((void**)&Bh,  g_Bh);
    cudaGetSymbolAddress((void**)&W1T, g_W1T);
    cudaGetSymbolAddress((void**)&Xc,  g_Xc);
    cudaGetSymbolAddress((void**)&Ft,  g_Ft);
    cudaGetSymbolAddress((void**)&H,   g_H);
    cudaGetSymbolAddress((void**)&s1,  g_s1);
    cudaGetSymbolAddress((void**)&t1,  g_t1);
    cudaGetSymbolAddress((void**)&s2,  g_s2);
    cudaGetSymbolAddress((void**)&t2,  g_t2);

    const int NOGRP = 1 << 30;

    // prep (independent of ROI path)
    bn_prep<<<2, 256>>>(bn1g, bn1b, bn1m, bn1v, s1, t1, 512);
    bn_prep<<<1, 256>>>(bn2g, bn2b, bn2m, bn2v, s2, t2, 256);
    expand_w<<<8192, 256>>>(conv1_w, W2a, 1024, 512);
    expand_w<<<4096, 256>>>(conv2_w, W2b, 512, 256);
    transpose_w1d<<<8192, 256>>>(conv1d_w, W1T);

    // ROI align -> X[r][ci*9+p]
    roi_kernel<<<RR, 256>>>(fmap, boxes, X);

    // conv1 (+bn1+leaky): Y1[1088,4608] = X[1088,9216] * W2a
    sgemm<<<dim3(36, 9), 256>>>(X, W2a, Y1, RR, NC1, K1,
                                K1, NC1, NC1, NOGRP, 0, s1, t1, 9, 1);
    // conv2 (+bn2+leaky): Y2[1088,2304] = Y1 * W2b
    sgemm<<<dim3(18, 9), 256>>>(Y1, W2b, Y2, RR, NC2, NC1,
                                NC1, NC2, NC2, NOGRP, 0, s2, t2, 9, 1);

    // behavior assemble (zero-padded for conv1d im2col-by-stride)
    assemble_bh<<<PP * 66, 256>>>(Y2, pid, Bh);

    // conv1d (+bias): Xc[1280,2304] = Bh-rows * W1T ; row (p,b) -> Bh+p*66*2304+b*2304, K=6912
    sgemm<<<dim3(18, 10), 256>>>(Bh, W1T, Xc, PP * 64, NC2, 3 * NC2,
                                 NC2, NC2, NC2, 64, 66LL * NC2,
                                 nullptr, conv1d_b, 1, 0);

    // gather feats
    gather_feats<<<BB * NN, 256>>>(Xc, pid, Ft);

    // fc1 (+bias, relu): H[1024,1024] = Ft[1024,2304] * fc1_w
    sgemm<<<dim3(8, 8), 256>>>(Ft, fc1_w, H, BB * NN, 1024, NC2,
                               NC2, 1024, 1024, NOGRP, 0, nullptr, fc1_b, 1, 2);
    // fc2 (+bias): out[1024,30] = H * fc2_w
    sgemm<<<dim3(1, 8), 256>>>(H, fc2_w, out, BB * NN, NBB, 1024,
                               1024, NBB, NBB, NOGRP, 0, nullptr, fc2_b, 1, 0);
}

// round 16
// speedup vs baseline: 1.6407x; 1.6407x over previous
#include <cuda_runtime.h>
#include <cuda_bf16.h>
#include <mma.h>
#include <math.h>

using namespace nvcuda;

// Problem constants
#define BB 64
#define NN 16
#define PP 20
#define NBB 30
#define CC 1024
#define FF 14
#define RR 1088          // BB*(NN+1) ROIs: [0,1024) individual, [1024,1088) global
#define K1 9216          // CC*9
#define NC1 4608         // 512*9
#define NC2 2304         // 256*9

typedef __nv_bfloat16 bf16;

// ---------------- scratch (static device globals; no allocation) ----------------
__device__ __align__(256) bf16  g_Xh  [(size_t)RR * K1];
__device__ __align__(256) bf16  g_Xl  [(size_t)RR * K1];
__device__ __align__(256) bf16  g_W2ah[(size_t)K1 * NC1];
__device__ __align__(256) bf16  g_W2al[(size_t)K1 * NC1];
__device__ __align__(256) bf16  g_Y1h [(size_t)RR * NC1];
__device__ __align__(256) bf16  g_Y1l [(size_t)RR * NC1];
__device__ __align__(256) bf16  g_W2bh[(size_t)NC1 * NC2];
__device__ __align__(256) bf16  g_W2bl[(size_t)NC1 * NC2];
__device__ __align__(256) float g_Y2  [(size_t)RR * NC2];
__device__ __align__(256) bf16  g_Bhh [(size_t)PP * 66 * NC2];
__device__ __align__(256) bf16  g_Bhl [(size_t)PP * 66 * NC2];
__device__ __align__(256) bf16  g_W1Th[(size_t)3 * NC2 * NC2];
__device__ __align__(256) bf16  g_W1Tl[(size_t)3 * NC2 * NC2];
__device__ __align__(256) float g_Xc  [(size_t)PP * 64 * NC2];
__device__ __align__(256) bf16  g_Fth [(size_t)BB * NN * NC2];
__device__ __align__(256) bf16  g_Ftl [(size_t)BB * NN * NC2];
__device__ __align__(256) bf16  g_FWh [(size_t)NC2 * 1024];
__device__ __align__(256) bf16  g_FWl [(size_t)NC2 * 1024];
__device__ __align__(256) float g_H   [(size_t)BB * NN * 1024];
__device__ float g_s1[512], g_t1[512], g_s2[256], g_t2[256];

__device__ __forceinline__ void split_bf(float v, bf16& h, bf16& l) {
    h = __float2bfloat16(v);
    l = __float2bfloat16(v - __bfloat162float(h));
}

// ---------------- BN scale/shift precompute ----------------
__global__ void bn_prep(const float* __restrict__ g, const float* __restrict__ b,
                        const float* __restrict__ m, const float* __restrict__ v,
                        float* __restrict__ s, float* __restrict__ t, int n) {
    int i = blockIdx.x * blockDim.x + threadIdx.x;
    if (i < n) {
        float sc = g[i] * rsqrtf(v[i] + 1e-5f);
        s[i] = sc;
        t[i] = b[i] - m[i] * sc;
    }
}

// ---------------- conv weight expansion (scale folded) + bf16 split ----------------
// W2[(ci*9+p)][co*9+q] = s[co] * w[co][ci][py-qy+1][px-qx+1] (0 if stencil OOB)
__global__ void expand_w_bf(const float* __restrict__ w, const float* __restrict__ s,
                            bf16* __restrict__ Wh, bf16* __restrict__ Wl,
                            int Cin, int Cout) {
    size_t total = (size_t)Cin * 9 * Cout * 9;
    int ncol = Cout * 9;
    for (size_t i = (size_t)blockIdx.x * blockDim.x + threadIdx.x; i < total;
         i += (size_t)gridDim.x * blockDim.x) {
        int col = (int)(i % ncol);
        size_t row = i / ncol;
        int p  = (int)(row % 9);
        int ci = (int)(row / 9);
        int q  = col % 9;
        int co = col / 9;
        int ky = (p / 3) - (q / 3) + 1;
        int kx = (p % 3) - (q % 3) + 1;
        float val = 0.f;
        if ((unsigned)ky < 3u && (unsigned)kx < 3u)
            val = w[(((size_t)co * Cin + ci) * 3 + ky) * 3 + kx] * s[co];
        bf16 h, l; split_bf(val, h, l);
        Wh[i] = h; Wl[i] = l;
    }
}

// conv1d weights [ko][ki][dt] -> WT[(dt*2304+ki)][ko], bf16 split
__global__ void transpose_w1d_bf(const float* __restrict__ w,
                                 bf16* __restrict__ WTh, bf16* __restrict__ WTl) {
    size_t total = (size_t)3 * NC2 * NC2;
    for (size_t i = (size_t)blockIdx.x * blockDim.x + threadIdx.x; i < total;
         i += (size_t)gridDim.x * blockDim.x) {
        int ko = (int)(i % NC2);
        size_t rest = i / NC2;
        int ki = (int)(rest % NC2);
        int dt = (int)(rest / NC2);
        bf16 h, l; split_bf(w[((size_t)ko * NC2 + ki) * 3 + dt], h, l);
        WTh[i] = h; WTl[i] = l;
    }
}

// generic f32 -> bf16 hi/lo split
__global__ void split_f32(const float* __restrict__ src,
                          bf16* __restrict__ h, bf16* __restrict__ l, size_t n) {
    for (size_t i = (size_t)blockIdx.x * blockDim.x + threadIdx.x; i < n;
         i += (size_t)gridDim.x * blockDim.x) {
        bf16 hh, ll; split_bf(src[i], hh, ll);
        h[i] = hh; l[i] = ll;
    }
}

// ---------------- ROI align (writes bf16 hi/lo) ----------------
__global__ void roi_kernel(const float* __restrict__ fmap, const float* __restrict__ boxes,
                           bf16* __restrict__ Xh, bf16* __restrict__ Xl) {
    int r = blockIdx.x;
    int b;
    float bx1, by1, bx2, by2;
    if (r >= BB * NN) {
        b = r - BB * NN;
        bx1 = 0.f; by1 = 0.f; bx2 = (float)FF; by2 = (float)FF;
    } else {
        b = r / NN;
        const float* p = boxes + (size_t)r * 4;
        bx1 = p[0]; by1 = p[1]; bx2 = p[2]; by2 = p[3];
    }
    __shared__ int   i0s[12], i1s[12];
    __shared__ float wgt[12];
    int tid = threadIdx.x;
    if (tid < 12) {
        int s = tid % 6;
        bool isY = tid < 6;
        float lo  = isY ? by1 : bx1;
        float hi  = isY ? by2 : bx2;
        float ext = fmaxf(hi - lo, 1.0f);
        float v = lo + (s + 0.5f) * 0.5f * (ext * (1.0f / 3.0f));
        v = fminf(fmaxf(v, 0.0f), 13.0f);
        float fl = floorf(v);
        int i0 = (int)fl;
        i0s[tid] = i0;
        i1s[tid] = min(i0 + 1, 13);
        wgt[tid] = v - fl;
    }
    __syncthreads();
    const float* fm = fmap + (size_t)b * (CC * FF * FF);
    size_t ro = (size_t)r * K1;
    for (int idx = tid; idx < CC * 9; idx += blockDim.x) {
        int c = idx / 9, q = idx - c * 9;
        int oy = q / 3, ox = q - oy * 3;
        const float* f = fm + c * (FF * FF);
        float acc = 0.f;
#pragma unroll
        for (int dy = 0; dy < 2; dy++) {
            int sy = oy * 2 + dy;
            int ya = i0s[sy], yb = i1s[sy];
            float wy = wgt[sy];
#pragma unroll
            for (int dx = 0; dx < 2; dx++) {
                int sx = ox * 2 + dx;
                int xa = i0s[6 + sx], xb = i1s[6 + sx];
                float wx = wgt[6 + sx];
                float v00 = f[ya * FF + xa], v01 = f[ya * FF + xb];
                float v10 = f[yb * FF + xa], v11 = f[yb * FF + xb];
                float top = v00 + (v01 - v00) * wx;
                float bot = v10 + (v11 - v10) * wx;
                acc += top + (bot - top) * wy;
            }
        }
        bf16 h, l; split_bf(acc * 0.25f, h, l);
        Xh[ro + idx] = h; Xl[ro + idx] = l;
    }
}

// ---------------- behavior assemble (deterministic, no atomics; bf16 split out) ----------------
__global__ void assemble_bh(const float* __restrict__ Y2, const int* __restrict__ pid,
                            bf16* __restrict__ Bhh, bf16* __restrict__ Bhl) {
    int blk = blockIdx.x;          // 0..PP*66-1
    int p = blk / 66, bb = blk % 66;
    size_t o = (size_t)blk * NC2;
    if (bb == 0 || bb == 65) {
        bf16 z = __float2bfloat16(0.f);
        for (int k = threadIdx.x; k < NC2; k += blockDim.x) { Bhh[o + k] = z; Bhl[o + k] = z; }
        return;
    }
    int b = bb - 1;
    __shared__ int rows[NN];
    __shared__ int cnt;
    if (threadIdx.x == 0) {
        int c = 0;
        for (int n = 0; n < NN; n++)
            if (pid[b * NN + n] == p) rows[c++] = b * NN + n;
        cnt = c;
    }
    __syncthreads();
    const float* gsrc = Y2 + (size_t)(BB * NN + b) * NC2;
    int c = cnt;
    for (int k = threadIdx.x; k < NC2; k += blockDim.x) {
        float v = gsrc[k];
        for (int j = 0; j < c; j++) v += Y2[(size_t)rows[j] * NC2 + k];
        bf16 h, l; split_bf(v, h, l);
        Bhh[o + k] = h; Bhl[o + k] = l;
    }
}

// feats[(b*16+n)][k] = Xc[(pid[b,n]*64 + b)][k], split to bf16
__global__ void gather_feats(const float* __restrict__ Xc, const int* __restrict__ pid,
                             bf16* __restrict__ Fh, bf16* __restrict__ Fl) {
    int m = blockIdx.x;            // 0..1023
    int b = m / NN;
    int p = pid[m];
    const float* src = Xc + ((size_t)p * 64 + b) * NC2;
    size_t o = (size_t)m * NC2;
    for (int k = threadIdx.x; k < NC2; k += blockDim.x) {
        bf16 h, l; split_bf(src[k], h, l);
        Fh[o + k] = h; Fl[o + k] = l;
    }
}

// ---------------- bf16 3-pass tensor-core GEMM, 128x128x32 tiles ----------------
// C[M,N] = A[M,K]*B[K,N] where A,B are hi/lo bf16 splits of fp32 operands.
// acc += Ah*Bh + Ah*Bl + Al*Bh (fp32 accumulate) -> ~16-bit mantissa accuracy.
// A logical row m at (m/grp)*gstride + (m%grp)*lda (element offsets).
// Requires: N % 128 == 0, K % 32 == 0, lda/ldb/gstride % 8 == 0.
// Epilogue: v += bias[gn/ediv]; act 0=none 1=leaky(0.1) 2=relu;
// output: if C != null -> fp32 C; else bf16 split (Ch, Cl).
__global__ __launch_bounds__(256, 1)
void bmma(const bf16* __restrict__ Ah, const bf16* __restrict__ Al,
          const bf16* __restrict__ Bh, const bf16* __restrict__ Bl,
          float* __restrict__ C, bf16* __restrict__ Ch, bf16* __restrict__ Cl,
          int M, int N, int K, int lda, int ldb, int ldc,
          int grp, long long gstride,
          const float* __restrict__ bias, int ediv, int act) {
    __shared__ bf16 As[2][128][40];   // padded stride 40 (80B, 16B-aligned, LDSM conflict-free)
    __shared__ bf16 Bs[2][32][136];   // padded stride 136 (272B)
    __shared__ float stage[8][256];

    int t = threadIdx.x;
    int n0 = blockIdx.x * 128, m0 = blockIdx.y * 128;
    int wid = t >> 5, lane = t & 31;
    int wm = wid >> 2, wn = wid & 3;   // 2 x 4 warp grid, warp tile 64 x 32

    wmma::fragment<wmma::accumulator, 16, 16, 16, float> acc[4][2];
#pragma unroll
    for (int mi = 0; mi < 4; mi++)
#pragma unroll
        for (int ni = 0; ni < 2; ni++) wmma::fill_fragment(acc[mi][ni], 0.f);

    for (int k0 = 0; k0 < K; k0 += 32) {
        // A tile: 128x32 per half; 512 float4 loads per half, 2 per thread
#pragma unroll
        for (int i = 0; i < 2; i++) {
            int c = t + i * 256;
            int row = c >> 2;
            int col = (c & 3) * 8;
            int gm = m0 + row;
            float4 vh = make_float4(0.f, 0.f, 0.f, 0.f);
            float4 vl = vh;
            if (gm < M) {
                long long base = (long long)(gm / grp) * gstride +
                                 (long long)(gm % grp) * (long long)lda + k0 + col;
                vh = *reinterpret_cast<const float4*>(Ah + base);
                vl = *reinterpret_cast<const float4*>(Al + base);
            }
            *reinterpret_cast<float4*>(&As[0][row][col]) = vh;
            *reinterpret_cast<float4*>(&As[1][row][col]) = vl;
        }
        // B tile: 32x128 per half
#pragma unroll
        for (int i = 0; i < 2; i++) {
            int c = t + i * 256;
            int row = c >> 4;
            int col = (c & 15) * 8;
            long long base = (long long)(k0 + row) * ldb + n0 + col;
            *reinterpret_cast<float4*>(&Bs[0][row][col]) =
                *reinterpret_cast<const float4*>(Bh + base);
            *reinterpret_cast<float4*>(&Bs[1][row][col]) =
                *reinterpret_cast<const float4*>(Bl + base);
        }
        __syncthreads();
#pragma unroll
        for (int kk = 0; kk < 32; kk += 16) {
            wmma::fragment<wmma::matrix_a, 16, 16, 16, bf16, wmma::row_major> a_h[4], a_l[4];
#pragma unroll
            for (int mi = 0; mi < 4; mi++) {
                wmma::load_matrix_sync(a_h[mi], &As[0][wm * 64 + mi * 16][kk], 40);
                wmma::load_matrix_sync(a_l[mi], &As[1][wm * 64 + mi * 16][kk], 40);
            }
#pragma unroll
            for (int ni = 0; ni < 2; ni++) {
                wmma::fragment<wmma::matrix_b, 16, 16, 16, bf16, wmma::row_major> b_h, b_l;
                wmma::load_matrix_sync(b_h, &Bs[0][kk][wn * 32 + ni * 16], 136);
                wmma::load_matrix_sync(b_l, &Bs[1][kk][wn * 32 + ni * 16], 136);
#pragma unroll
                for (int mi = 0; mi < 4; mi++) {
                    wmma::mma_sync(acc[mi][ni], a_h[mi], b_h, acc[mi][ni]);
                    wmma::mma_sync(acc[mi][ni], a_h[mi], b_l, acc[mi][ni]);
                    wmma::mma_sync(acc[mi][ni], a_l[mi], b_h, acc[mi][ni]);
                }
            }
        }
        __syncthreads();
    }

    // epilogue via per-warp smem staging (layout-agnostic)
#pragma unroll
    for (int mi = 0; mi < 4; mi++) {
#pragma unroll
        for (int ni = 0; ni < 2; ni++) {
            wmma::store_matrix_sync(stage[wid], acc[mi][ni], 16, wmma::mem_row_major);
            __syncwarp();
            int tm = m0 + wm * 64 + mi * 16;
            int tn = n0 + wn * 32 + ni * 16;
#pragma unroll
            for (int i = 0; i < 8; i++) {
                int e = lane * 8 + i;
                int r = e >> 4, cx = e & 15;
                int gm = tm + r, gn = tn + cx;
                if (gm < M) {
                    float v = stage[wid][e];
                    if (bias) v += bias[gn / ediv];
                    if (act == 1) v = v > 0.f ? v : 0.1f * v;
                    else if (act == 2) v = fmaxf(v, 0.f);
                    long long o = (long long)gm * ldc + gn;
                    if (C) C[o] = v;
                    else {
                        bf16 h, l; split_bf(v, h, l);
                        Ch[o] = h; Cl[o] = l;
                    }
                }
            }
            __syncwarp();
        }
    }
}

// ---------------- fp32 tiled SGEMM (kept for tiny fc2) ----------------
__global__ __launch_bounds__(256, 2)
void sgemm(const float* __restrict__ A, const float* __restrict__ Bm,
           float* __restrict__ C,
           int M, int N, int K,
           int lda, int ldb, int ldc,
           const float* __restrict__ eshift, int act) {
    const int BM = 128, BN = 128, BK = 16;
    __shared__ float As[BK][BM + 4];
    __shared__ float Bs[BK][BN];
    int t = threadIdx.x;
    int n0 = blockIdx.x * BN;
    int m0 = blockIdx.y * BM;
    int tx = t % 16, ty = t / 16;
    float acc[8][8];
#pragma unroll
    for (int i = 0; i < 8; i++)
#pragma unroll
        for (int j = 0; j < 8; j++) acc[i][j] = 0.f;

    int arow0 = t >> 2;
    int acol  = (t & 3) * 4;
    int bcol  = t % 128;
    int brow0 = t / 128;

    for (int k0 = 0; k0 < K; k0 += BK) {
#pragma unroll
        for (int i = 0; i < 2; i++) {
            int lrow = arow0 + i * 64;
            int gm = m0 + lrow;
            float4 v = make_float4(0.f, 0.f, 0.f, 0.f);
            if (gm < M)
                v = *reinterpret_cast<const float4*>(A + (long long)gm * lda + k0 + acol);
            As[acol + 0][lrow] = v.x;
            As[acol + 1][lrow] = v.y;
            As[acol + 2][lrow] = v.z;
            As[acol + 3][lrow] = v.w;
        }
        int gn = n0 + bcol;
#pragma unroll
        for (int i = 0; i < 8; i++) {
            int lrow = brow0 + i * 2;
            float v = 0.f;
            if (gn < N) v = Bm[(long long)(k0 + lrow) * ldb + gn];
            Bs[lrow][bcol] = v;
        }
        __syncthreads();
#pragma unroll
        for (int k = 0; k < BK; k++) {
            float4 a0 = *reinterpret_cast<const float4*>(&As[k][ty * 8]);
            float4 a1 = *reinterpret_cast<const float4*>(&As[k][ty * 8 + 4]);
            float4 b0 = *reinterpret_cast<const float4*>(&Bs[k][tx * 8]);
            float4 b1 = *reinterpret_cast<const float4*>(&Bs[k][tx * 8 + 4]);
            float av[8] = {a0.x, a0.y, a0.z, a0.w, a1.x, a1.y, a1.z, a1.w};
            float bv[8] = {b0.x, b0.y, b0.z, b0.w, b1.x, b1.y, b1.z, b1.w};
#pragma unroll
            for (int i = 0; i < 8; i++)
#pragma unroll
                for (int j = 0; j < 8; j++)
                    acc[i][j] = fmaf(av[i], bv[j], acc[i][j]);
        }
        __syncthreads();
    }
#pragma unroll
    for (int i = 0; i < 8; i++) {
        int gm = m0 + ty * 8 + i;
        if (gm >= M) continue;
#pragma unroll
        for (int j = 0; j < 8; j++) {
            int gn = n0 + tx * 8 + j;
            if (gn >= N) continue;
            float x = acc[i][j];
            if (eshift) x += eshift[gn];
            if (act == 2) x = fmaxf(x, 0.f);
            C[(long long)gm * ldc + gn] = x;
        }
    }
}

// ---------------- launch ----------------
extern "C" void kernel_launch(void* const* d_in, const int* in_sizes, int n_in,
                              void* d_out, int out_size) {
    const float* fmap     = (const float*)d_in[0];
    const float* boxes    = (const float*)d_in[1];
    const int*   pid      = (const int*)  d_in[2];
    const float* conv1_w  = (const float*)d_in[3];
    const float* bn1g     = (const float*)d_in[4];
    const float* bn1b     = (const float*)d_in[5];
    const float* bn1m     = (const float*)d_in[6];
    const float* bn1v     = (const float*)d_in[7];
    const float* conv2_w  = (const float*)d_in[8];
    const float* bn2g     = (const float*)d_in[9];
    const float* bn2b     = (const float*)d_in[10];
    const float* bn2m     = (const float*)d_in[11];
    const float* bn2v     = (const float*)d_in[12];
    const float* conv1d_w = (const float*)d_in[13];
    const float* conv1d_b = (const float*)d_in[14];
    const float* fc1_w    = (const float*)d_in[15];
    const float* fc1_b    = (const float*)d_in[16];
    const float* fc2_w    = (const float*)d_in[17];
    const float* fc2_b    = (const float*)d_in[18];
    float* out = (float*)d_out;

    bf16 *Xh, *Xl, *W2ah, *W2al, *Y1h, *Y1l, *W2bh, *W2bl;
    bf16 *Bhh, *Bhl, *W1Th, *W1Tl, *Fth, *Ftl, *FWh, *FWl;
    float *Y2, *Xc, *H, *s1, *t1, *s2, *t2;
    cudaGetSymbolAddress((void**)&Xh,   g_Xh);
    cudaGetSymbolAddress((void**)&Xl,   g_Xl);
    cudaGetSymbolAddress((void**)&W2ah, g_W2ah);
    cudaGetSymbolAddress((void**)&W2al, g_W2al);
    cudaGetSymbolAddress((void**)&Y1h,  g_Y1h);
    cudaGetSymbolAddress((void**)&Y1l,  g_Y1l);
    cudaGetSymbolAddress((void**)&W2bh, g_W2bh);
    cudaGetSymbolAddress((void**)&W2bl, g_W2bl);
    cudaGetSymbolAddress((void**)&Y2,   g_Y2);
    cudaGetSymbolAddress((void**)&Bhh,  g_Bhh);
    cudaGetSymbolAddress((void**)&Bhl,  g_Bhl);
    cudaGetSymbolAddress((void**)&W1Th, g_W1Th);
    cudaGetSymbolAddress((void**)&W1Tl, g_W1Tl);
    cudaGetSymbolAddress((void**)&Xc,   g_Xc);
    cudaGetSymbolAddress((void**)&Fth,  g_Fth);
    cudaGetSymbolAddress((void**)&Ftl,  g_Ftl);
    cudaGetSymbolAddress((void**)&FWh,  g_FWh);
    cudaGetSymbolAddress((void**)&FWl,  g_FWl);
    cudaGetSymbolAddress((void**)&H,    g_H);
    cudaGetSymbolAddress((void**)&s1,   g_s1);
    cudaGetSymbolAddress((void**)&t1,   g_t1);
    cudaGetSymbolAddress((void**)&s2,   g_s2);
    cudaGetSymbolAddress((void**)&t2,   g_t2);

    const int NOGRP = 1 << 30;

    // prep (independent of ROI path)
    bn_prep<<<2, 256>>>(bn1g, bn1b, bn1m, bn1v, s1, t1, 512);
    bn_prep<<<1, 256>>>(bn2g, bn2b, bn2m, bn2v, s2, t2, 256);
    expand_w_bf<<<8192, 256>>>(conv1_w, s1, W2ah, W2al, 1024, 512);
    expand_w_bf<<<4096, 256>>>(conv2_w, s2, W2bh, W2bl, 512, 256);
    transpose_w1d_bf<<<8192, 256>>>(conv1d_w, W1Th, W1Tl);
    split_f32<<<2048, 256>>>(fc1_w, FWh, FWl, (size_t)NC2 * 1024);

    // ROI align -> X (bf16 hi/lo) [1088][9216]
    roi_kernel<<<RR, 256>>>(fmap, boxes, Xh, Xl);

    // conv1 (+bn1 shift + leaky): Y1[1088,4608]
    bmma<<<dim3(36, 9), 256>>>(Xh, Xl, W2ah, W2al, nullptr, Y1h, Y1l,
                               RR, NC1, K1, K1, NC1, NC1, NOGRP, 0, t1, 9, 1);
    // conv2 (+bn2 shift + leaky): Y2[1088,2304] fp32
    bmma<<<dim3(18, 9), 256>>>(Y1h, Y1l, W2bh, W2bl, Y2, nullptr, nullptr,
                               RR, NC2, NC1, NC1, NC2, NC2, NOGRP, 0, t2, 9, 1);

    // behavior assemble (zero-padded for conv1d im2col-by-stride), bf16 split
    assemble_bh<<<PP * 66, 256>>>(Y2, pid, Bhh, Bhl);

    // conv1d (+bias): Xc[1280,2304] fp32; grouped-A rows (p,b), K=6912
    bmma<<<dim3(18, 10), 256>>>(Bhh, Bhl, W1Th, W1Tl, Xc, nullptr, nullptr,
                                PP * 64, NC2, 3 * NC2, NC2, NC2, NC2,
                                64, 66LL * NC2, conv1d_b, 1, 0);

    // gather feats -> bf16 split
    gather_feats<<<BB * NN, 256>>>(Xc, pid, Fth, Ftl);

    // fc1 (+bias, relu): H[1024,1024] fp32
    bmma<<<dim3(8, 8), 256>>>(Fth, Ftl, FWh, FWl, H, nullptr, nullptr,
                              BB * NN, 1024, NC2, NC2, 1024, 1024,
                              NOGRP, 0, fc1_b, 1, 2);

    // fc2 (+bias): out[1024,30] = H * fc2_w  (tiny, fp32 FFMA path)
    sgemm<<<dim3(1, 8), 256>>>(H, fc2_w, out, BB * NN, NBB, 1024,
                               1024, NBB, NBB, fc2_b, 0);
}